// round 16
// baseline (speedup 1.0000x reference)
#include <cuda_runtime.h>
#include <math.h>
#include <stdint.h>

#define B_   8192
#define F_   32
#define P_   512
#define H_   256
#define BM   16
#define NT   256
#define XP   516          // xn pitch (floats); 516 % 32 == 4 -> conflict-free frag gathers
#define KCT  8            // k per chunk = one m16n8k8 step
#define WP   12           // sW pitch (floats); 12 % 32 -> banks 12n+q all distinct

// smem layout (floats)
#define OFF_XN     0
#define OFF_WHI    (BM * XP)               // 8256   (16B aligned: 8256*4 % 16 == 0)
#define OFF_WLO    (OFF_WHI + H_ * WP)     // 11328
#define OFF_WNORM  (OFF_WLO + H_ * WP)     // 14400
#define OFF_SB1    (OFF_WNORM + BM * F_)   // 14912
#define OFF_SW2    (OFF_SB1 + H_)          // 15168
#define OFF_RED    (OFF_SW2 + H_)          // 15424
#define OFF_SLEN   (OFF_RED + BM * 8)      // 15552
#define SMEM_FLOATS (OFF_SLEN + BM)        // 15568 floats = 62.3 KB

__device__ __align__(16) float g_Whi[H_ * P_];
__device__ __align__(16) float g_Wlo[H_ * P_];

__device__ __forceinline__ uint32_t f2tf(float f) {
    uint32_t r;
    asm("cvt.rna.tf32.f32 %0, %1;" : "=r"(r) : "f"(f));
    return r;
}

__device__ __forceinline__ void cp_async16(uint32_t dst, const void* src) {
    asm volatile("cp.async.cg.shared.global [%0], [%1], 16;" :: "r"(dst), "l"(src));
}
__device__ __forceinline__ void cp_commit() {
    asm volatile("cp.async.commit_group;" ::: "memory");
}
__device__ __forceinline__ void cp_wait0() {
    asm volatile("cp.async.wait_group 0;" ::: "memory");
}

__device__ __forceinline__ void mma8(float* c,
                                     uint32_t a0, uint32_t a1, uint32_t a2, uint32_t a3,
                                     uint32_t b0, uint32_t b1) {
    asm("mma.sync.aligned.m16n8k8.row.col.f32.tf32.tf32.f32 "
        "{%0,%1,%2,%3},{%4,%5,%6,%7},{%8,%9},{%0,%1,%2,%3};"
        : "+f"(c[0]), "+f"(c[1]), "+f"(c[2]), "+f"(c[3])
        : "r"(a0), "r"(a1), "r"(a2), "r"(a3), "r"(b0), "r"(b1));
}

// ---------------- prologue: split W1 into tf32 hi/lo ----------------
__global__ void k_prep(const float* __restrict__ W1) {
    const int i = blockIdx.x * blockDim.x + threadIdx.x;   // 0..32767 (float4 units)
    float4 v = ((const float4*)W1)[i];
    float4 hi, lo;
    hi.x = __uint_as_float(f2tf(v.x)); lo.x = __uint_as_float(f2tf(v.x - hi.x));
    hi.y = __uint_as_float(f2tf(v.y)); lo.y = __uint_as_float(f2tf(v.y - hi.y));
    hi.z = __uint_as_float(f2tf(v.z)); lo.z = __uint_as_float(f2tf(v.z - hi.z));
    hi.w = __uint_as_float(f2tf(v.w)); lo.w = __uint_as_float(f2tf(v.w - hi.w));
    ((float4*)g_Whi)[i] = hi;
    ((float4*)g_Wlo)[i] = lo;
}

__global__ __launch_bounds__(NT, 3)
void physchem_fused(const float* __restrict__ phys,
                    const float* __restrict__ ratios,
                    const int*   __restrict__ lengths,
                    const float* __restrict__ ln_gamma,
                    const float* __restrict__ ln_beta,
                    const float* __restrict__ b1,
                    const float* __restrict__ W2,
                    const float* __restrict__ b2,
                    float*       __restrict__ out)
{
    extern __shared__ float sm[];
    float* xn    = sm + OFF_XN;        // [BM][XP]
    float* sWhi  = sm + OFF_WHI;       // [H_][WP]
    float* sWlo  = sm + OFF_WLO;
    float* wnorm = sm + OFF_WNORM;     // [BM][F_]
    float* sb1   = sm + OFF_SB1;       // [H_]
    float* sw2   = sm + OFF_SW2;       // [H_]
    float* red   = sm + OFF_RED;       // [BM][8]
    int*   slen  = (int*)(sm + OFF_SLEN);

    const int tid  = threadIdx.x;
    const int wid  = tid >> 5;
    const int lane = tid & 31;
    const int b0   = blockIdx.x * BM;

    uint32_t smem_u32;
    asm("{ .reg .u64 t; cvta.to.shared.u64 t, %1; cvt.u32.u64 %0, t; }"
        : "=r"(smem_u32) : "l"((const void*)sm));
    const uint32_t whi_u32 = smem_u32 + OFF_WHI * 4;
    const uint32_t wlo_u32 = smem_u32 + OFF_WLO * 4;

    // ---------- A0: normalized weights + lengths + b1/W2 staging ----------------
    sb1[tid] = b1[tid];
    sw2[tid] = W2[tid];
    #pragma unroll
    for (int rr = 0; rr < 2; rr++) {
        const int r = wid * 2 + rr;
        const int b = b0 + r;
        const int len = lengths[b];
        if (lane == 0) slen[r] = len;
        float rv = (lane < len) ? ratios[b * F_ + lane] : 0.0f;
        float s = rv;
        #pragma unroll
        for (int o = 16; o > 0; o >>= 1) s += __shfl_xor_sync(0xffffffffu, s, o);
        wnorm[r * F_ + lane] = rv / (s + 1e-8f);  // zero for lane >= len
    }
    __syncthreads();

    // ---------- A1: weighted mix (R14 structure), float4 loads, f unroll x4 -----
    {
        const int q  = wid & 3;
        const int rh = (wid >> 2) * 8;
        const int v4 = q * 32 + lane;             // float4 index within row (0..127)
        for (int rr = 0; rr < 8; rr++) {
            const int r   = rh + rr;
            const int len = slen[r];
            const float*  wr = wnorm + r * F_;
            const float4* pp = (const float4*)(phys + (size_t)(b0 + r) * (F_ * P_)) + v4;
            float4 acc = make_float4(0.f, 0.f, 0.f, 0.f);
            const int f4 = (len + 3) & ~3;
            for (int f = 0; f < f4; f += 4) {
                const float w0 = wr[f + 0];
                const float w1 = wr[f + 1];
                const float w2_ = wr[f + 2];
                const float w3 = wr[f + 3];
                float4 u0 = pp[(f + 0) * (P_ / 4)];
                float4 u1 = pp[(f + 1) * (P_ / 4)];
                float4 u2 = pp[(f + 2) * (P_ / 4)];
                float4 u3 = pp[(f + 3) * (P_ / 4)];
                acc.x += w0*u0.x + w1*u1.x + w2_*u2.x + w3*u3.x;
                acc.y += w0*u0.y + w1*u1.y + w2_*u2.y + w3*u3.y;
                acc.z += w0*u0.z + w1*u1.z + w2_*u2.z + w3*u3.z;
                acc.w += w0*u0.w + w1*u1.w + w2_*u2.w + w3*u3.w;
            }
            ((float4*)(xn + r * XP))[v4] = acc;
        }
    }
    __syncthreads();

    // ---------- A2: LayerNorm in-place (warp w -> rows 2w, 2w+1) ----------------
    #pragma unroll
    for (int rr = 0; rr < 2; rr++) {
        const int r = wid * 2 + rr;
        float4 vv[4];
        float s = 0.0f, s2 = 0.0f;
        #pragma unroll
        for (int i = 0; i < 4; i++) {
            vv[i] = ((const float4*)(xn + r * XP))[lane + 32 * i];
            s  += vv[i].x + vv[i].y + vv[i].z + vv[i].w;
            s2 += vv[i].x * vv[i].x + vv[i].y * vv[i].y
                + vv[i].z * vv[i].z + vv[i].w * vv[i].w;
        }
        #pragma unroll
        for (int o = 16; o > 0; o >>= 1) {
            s  += __shfl_xor_sync(0xffffffffu, s,  o);
            s2 += __shfl_xor_sync(0xffffffffu, s2, o);
        }
        const float mu   = s * (1.0f / P_);
        const float var  = fmaxf(s2 * (1.0f / P_) - mu * mu, 0.0f);
        const float rstd = rsqrtf(var + 1e-5f);
        #pragma unroll
        for (int i = 0; i < 4; i++) {
            const int vi = lane + 32 * i;
            float4 g  = ((const float4*)ln_gamma)[vi];
            float4 be = ((const float4*)ln_beta)[vi];
            float4 o4;
            o4.x = (vv[i].x - mu) * rstd * g.x + be.x;
            o4.y = (vv[i].y - mu) * rstd * g.y + be.y;
            o4.z = (vv[i].z - mu) * rstd * g.z + be.z;
            o4.w = (vv[i].w - mu) * rstd * g.w + be.w;
            ((float4*)(xn + r * XP))[vi] = o4;
        }
    }

    // ---------- Phase B: 3xTF32 tensor-core GEMM --------------------------------
    // Warp wid owns cols [wid*32, wid*32+32) as 4 n8-tiles. 64 k8 chunks.
    const int q  = lane & 3;        // frag k offset
    const int rA = lane >> 2;       // frag row group

    float acc[4][4];
    #pragma unroll
    for (int t = 0; t < 4; t++)
        #pragma unroll
        for (int e = 0; e < 4; e++) acc[t][e] = 0.0f;

    for (int c = 0; c < P_ / KCT; c++) {          // 64 chunks
        const int kb = c * KCT;
        __syncthreads();                          // prev chunk consumed (also A2->B)
        // stage hi/lo chunk: thread tid handles row j = tid (8 floats each)
        {
            const float* sh = g_Whi + tid * P_ + kb;
            const float* sl = g_Wlo + tid * P_ + kb;
            cp_async16(whi_u32 + tid * (WP * 4),      sh);
            cp_async16(whi_u32 + tid * (WP * 4) + 16, sh + 4);
            cp_async16(wlo_u32 + tid * (WP * 4),      sl);
            cp_async16(wlo_u32 + tid * (WP * 4) + 16, sl + 4);
        }
        cp_commit();
        cp_wait0();
        __syncthreads();

        // A fragments (hi/lo) for this k8 step
        const float x0 = xn[rA * XP + kb + q];
        const float x1 = xn[(rA + 8) * XP + kb + q];
        const float x2 = xn[rA * XP + kb + q + 4];
        const float x3 = xn[(rA + 8) * XP + kb + q + 4];
        const uint32_t ah0 = f2tf(x0), ah1 = f2tf(x1), ah2 = f2tf(x2), ah3 = f2tf(x3);
        const uint32_t al0 = f2tf(x0 - __uint_as_float(ah0));
        const uint32_t al1 = f2tf(x1 - __uint_as_float(ah1));
        const uint32_t al2 = f2tf(x2 - __uint_as_float(ah2));
        const uint32_t al3 = f2tf(x3 - __uint_as_float(ah3));

        #pragma unroll
        for (int t = 0; t < 4; t++) {
            const int n = wid * 32 + t * 8 + rA;  // B frag n = lane/4 within tile
            const uint32_t bh0 = *(const uint32_t*)(sWhi + n * WP + q);
            const uint32_t bh1 = *(const uint32_t*)(sWhi + n * WP + q + 4);
            const uint32_t bl0 = *(const uint32_t*)(sWlo + n * WP + q);
            const uint32_t bl1 = *(const uint32_t*)(sWlo + n * WP + q + 4);
            mma8(acc[t], ah0, ah1, ah2, ah3, bh0, bh1);
            mma8(acc[t], al0, al1, al2, al3, bh0, bh1);
            mma8(acc[t], ah0, ah1, ah2, ah3, bl0, bl1);
        }
    }

    // ---------- Epilogue: bias, ReLU, xW2, reduce, nan_to_num -------------------
    // C frag: acc[t][0,1] -> row rA, cols cb, cb+1 ; acc[t][2,3] -> row rA+8.
    float pA = 0.0f, pB = 0.0f;
    #pragma unroll
    for (int t = 0; t < 4; t++) {
        const int cb = wid * 32 + t * 8 + q * 2;
        const float bb0 = sb1[cb],  bb1v = sb1[cb + 1];
        const float ww0 = sw2[cb],  ww1  = sw2[cb + 1];
        pA += fmaxf(acc[t][0] + bb0, 0.0f) * ww0 + fmaxf(acc[t][1] + bb1v, 0.0f) * ww1;
        pB += fmaxf(acc[t][2] + bb0, 0.0f) * ww0 + fmaxf(acc[t][3] + bb1v, 0.0f) * ww1;
    }
    // sum across the 4 lanes sharing a row (lane%4 group)
    #pragma unroll
    for (int o = 1; o < 4; o <<= 1) {
        pA += __shfl_xor_sync(0xffffffffu, pA, o);
        pB += __shfl_xor_sync(0xffffffffu, pB, o);
    }
    if (q == 0) {
        red[rA * 8 + wid]       = pA;
        red[(rA + 8) * 8 + wid] = pB;
    }
    __syncthreads();

    if (tid < BM) {
        float y = b2[0];
        #pragma unroll
        for (int w = 0; w < 8; w++) y += red[tid * 8 + w];
        if (isnan(y)) y = 0.0f;
        else if (isinf(y)) y = (y > 0.0f) ? 3.4028234663852886e38f : -3.4028234663852886e38f;
        out[b0 + tid] = y;
    }
}

extern "C" void kernel_launch(void* const* d_in, const int* in_sizes, int n_in,
                              void* d_out, int out_size)
{
    const float* phys     = (const float*)d_in[0];
    const float* ratios   = (const float*)d_in[1];
    const int*   lengths  = (const int*)  d_in[2];
    const float* ln_gamma = (const float*)d_in[3];
    const float* ln_beta  = (const float*)d_in[4];
    const float* W1       = (const float*)d_in[5];
    const float* b1       = (const float*)d_in[6];
    const float* W2       = (const float*)d_in[7];
    const float* b2       = (const float*)d_in[8];
    float* out = (float*)d_out;

    const int smem_bytes = SMEM_FLOATS * (int)sizeof(float);
    cudaFuncSetAttribute(physchem_fused,
                         cudaFuncAttributeMaxDynamicSharedMemorySize, smem_bytes);

    k_prep<<<(H_ * P_ / 4 + NT - 1) / NT, NT>>>(W1);
    physchem_fused<<<B_ / BM, NT, smem_bytes>>>(
        phys, ratios, lengths, ln_gamma, ln_beta, b1, W2, b2, out);
}